// round 2
// baseline (speedup 1.0000x reference)
#include <cuda_runtime.h>
#include <math.h>

#define NN   50000
#define EE   800000
#define D    128
#define DOUT 10
#define GG   128

// ---------------- device scratch (no allocations allowed) ----------------
__device__ float g_h0[(size_t)NN * D];   // gemm output / agg input
__device__ float g_h1[(size_t)NN * D];   // agg output / next gemm input
__device__ int   g_deg[NN];
__device__ float g_dinv[NN];
__device__ int   g_rowptr[NN + 1];
__device__ int   g_fill[NN];
__device__ int   g_colsrc[EE];
__device__ float g_psum[GG * D];
__device__ int   g_pcnt[GG];

// ---------------- init ----------------
__global__ void k_init() {
    int i = blockIdx.x * blockDim.x + threadIdx.x;
    if (i < NN) { g_deg[i] = 1; g_fill[i] = 0; }
    if (i < GG * D) g_psum[i] = 0.0f;
    if (i < GG) g_pcnt[i] = 0;
}

__global__ void k_count(const int* __restrict__ ei) {
    int e = blockIdx.x * blockDim.x + threadIdx.x;
    if (e < EE) {
        int d = ei[EE + e];
        atomicAdd(&g_deg[d], 1);
    }
}

__global__ void k_dinv() {
    int i = blockIdx.x * blockDim.x + threadIdx.x;
    if (i < NN) g_dinv[i] = rsqrtf((float)g_deg[i]);
}

// single-block exclusive scan of (deg[i]-1) -> rowptr
__global__ void k_scan() {
    __shared__ int sums[1024];
    const int t = threadIdx.x;
    const int CH = (NN + 1023) / 1024;  // 49
    int start = t * CH;
    int end = start + CH;
    if (start > NN) start = NN;
    if (end > NN) end = NN;
    int local = 0;
    for (int i = start; i < end; i++) local += g_deg[i] - 1;
    sums[t] = local;
    __syncthreads();
    // Hillis-Steele inclusive scan
    for (int off = 1; off < 1024; off <<= 1) {
        int v = (t >= off) ? sums[t - off] : 0;
        __syncthreads();
        sums[t] += v;
        __syncthreads();
    }
    int run = (t == 0) ? 0 : sums[t - 1];
    for (int i = start; i < end; i++) {
        g_rowptr[i] = run;
        run += g_deg[i] - 1;
    }
    if (t == 1023) g_rowptr[NN] = sums[1023];
}

__global__ void k_fill(const int* __restrict__ ei) {
    int e = blockIdx.x * blockDim.x + threadIdx.x;
    if (e < EE) {
        int d = ei[EE + e];
        int s = ei[e];
        int pos = atomicAdd(&g_fill[d], 1);
        g_colsrc[g_rowptr[d] + pos] = s;
    }
}

// ---------------- GEMM: C[NN,128] = relu?(A)[NN,128] @ W[128,128] ----------------
// block: 256 threads, tile 64 rows x 128 cols. Dynamic smem: A tile (32KB) + W (64KB).
__global__ void k_gemm(const float* __restrict__ A, const float* __restrict__ W,
                       float* __restrict__ C, int relu) {
    extern __shared__ float sm[];
    float* As = sm;               // [64][128]
    float* Ws = sm + 64 * D;      // [128][128]
    const int t = threadIdx.x;
    const int row0 = blockIdx.x * 64;

    // stage W (128*128 floats = 4096 float4)
    for (int j = t; j < (D * D) / 4; j += 256)
        ((float4*)Ws)[j] = ((const float4*)W)[j];

    // stage A tile (64*128 floats = 2048 float4)
    for (int j = t; j < (64 * D) / 4; j += 256) {
        int r = j >> 5;          // /32 float4 per row
        int c4 = j & 31;
        float4 v = make_float4(0.f, 0.f, 0.f, 0.f);
        if (row0 + r < NN)
            v = ((const float4*)(A + (size_t)(row0 + r) * D))[c4];
        if (relu) {
            v.x = fmaxf(v.x, 0.f); v.y = fmaxf(v.y, 0.f);
            v.z = fmaxf(v.z, 0.f); v.w = fmaxf(v.w, 0.f);
        }
        ((float4*)(As + r * D))[c4] = v;
    }
    __syncthreads();

    const int w = t >> 5;   // warp: rows [w*8, w*8+8)
    const int l = t & 31;   // lane: cols [4l, 4l+4)
    float acc[8][4];
    #pragma unroll
    for (int i = 0; i < 8; i++)
        #pragma unroll
        for (int j = 0; j < 4; j++) acc[i][j] = 0.f;

    #pragma unroll 4
    for (int kk = 0; kk < D; kk++) {
        float4 b = ((const float4*)(Ws + kk * D))[l];
        #pragma unroll
        for (int i = 0; i < 8; i++) {
            float a = As[(w * 8 + i) * D + kk];  // warp-uniform -> broadcast
            acc[i][0] += a * b.x;
            acc[i][1] += a * b.y;
            acc[i][2] += a * b.z;
            acc[i][3] += a * b.w;
        }
    }

    #pragma unroll
    for (int i = 0; i < 8; i++) {
        int r = row0 + w * 8 + i;
        if (r < NN) {
            float4 o = make_float4(acc[i][0], acc[i][1], acc[i][2], acc[i][3]);
            ((float4*)(C + (size_t)r * D))[l] = o;
        }
    }
}

// ---------------- aggregation: out[i] = dinv[i]*(h[i]*dinv[i] + sum_e h[src]*dinv[src]) + b
// one warp per node, lane handles 4 features (float4)
__global__ void k_agg(const float* __restrict__ H, const float* __restrict__ bias,
                      float* __restrict__ O) {
    int warp = (blockIdx.x * blockDim.x + threadIdx.x) >> 5;
    int lane = threadIdx.x & 31;
    if (warp >= NN) return;
    const int i = warp;
    const float di = g_dinv[i];

    float4 acc = ((const float4*)(H + (size_t)i * D))[lane];
    acc.x *= di; acc.y *= di; acc.z *= di; acc.w *= di;

    const int e0 = g_rowptr[i], e1 = g_rowptr[i + 1];
    for (int e = e0; e < e1; e++) {
        int s = g_colsrc[e];
        float ds = g_dinv[s];
        float4 v = ((const float4*)(H + (size_t)s * D))[lane];
        acc.x += v.x * ds; acc.y += v.y * ds;
        acc.z += v.z * ds; acc.w += v.w * ds;
    }

    float4 b4 = ((const float4*)bias)[lane];
    float4 o;
    o.x = acc.x * di + b4.x;
    o.y = acc.y * di + b4.y;
    o.z = acc.z * di + b4.z;
    o.w = acc.w * di + b4.w;
    ((float4*)(O + (size_t)i * D))[lane] = o;
}

// ---------------- mean pool (atomic accumulate) ----------------
__global__ void k_pool(const float* __restrict__ H, const int* __restrict__ batch) {
    int warp = (blockIdx.x * blockDim.x + threadIdx.x) >> 5;
    int lane = threadIdx.x & 31;
    if (warp >= NN) return;
    const int i = warp;
    const int g = batch[i];
    float4 v = ((const float4*)(H + (size_t)i * D))[lane];
    float* dst = g_psum + g * D + lane * 4;
    atomicAdd(dst + 0, v.x);
    atomicAdd(dst + 1, v.y);
    atomicAdd(dst + 2, v.z);
    atomicAdd(dst + 3, v.w);
    if (lane == 0) atomicAdd(&g_pcnt[g], 1);
}

// ---------------- head: mean -> logits -> log_softmax ----------------
__global__ void k_final(const float* __restrict__ Wl, const float* __restrict__ bl,
                        float* __restrict__ out) {
    int g = threadIdx.x;
    if (g >= GG) return;
    float cnt = (float)g_pcnt[g];
    float inv = 1.0f / fmaxf(cnt, 1.0f);
    float logits[DOUT];
    #pragma unroll
    for (int d = 0; d < DOUT; d++) logits[d] = bl[d];
    for (int f = 0; f < D; f++) {
        float p = g_psum[g * D + f] * inv;
        #pragma unroll
        for (int d = 0; d < DOUT; d++)
            logits[d] += p * Wl[f * DOUT + d];
    }
    float m = logits[0];
    #pragma unroll
    for (int d = 1; d < DOUT; d++) m = fmaxf(m, logits[d]);
    float sum = 0.f;
    #pragma unroll
    for (int d = 0; d < DOUT; d++) sum += expf(logits[d] - m);
    float lse = m + logf(sum);
    #pragma unroll
    for (int d = 0; d < DOUT; d++) out[g * DOUT + d] = logits[d] - lse;
}

// ---------------- launch ----------------
extern "C" void kernel_launch(void* const* d_in, const int* in_sizes, int n_in,
                              void* d_out, int out_size) {
    const float* x     = (const float*)d_in[0];
    const int*   ei    = (const int*)d_in[1];    // edge_index delivered as int32
    const int*   batch = (const int*)d_in[2];    // batch delivered as int32
    const float* W1 = (const float*)d_in[3];
    const float* b1 = (const float*)d_in[4];
    const float* W2 = (const float*)d_in[5];
    const float* b2 = (const float*)d_in[6];
    const float* W3 = (const float*)d_in[7];
    const float* b3 = (const float*)d_in[8];
    const float* Wl = (const float*)d_in[9];
    const float* bl = (const float*)d_in[10];
    float* out = (float*)d_out;

    const size_t gemm_smem = (64 * D + D * D) * sizeof(float);  // 96 KB
    cudaFuncSetAttribute(k_gemm, cudaFuncAttributeMaxDynamicSharedMemorySize,
                         (int)gemm_smem);

    float *h0, *h1;
    cudaGetSymbolAddress((void**)&h0, g_h0);
    cudaGetSymbolAddress((void**)&h1, g_h1);

    const int TB = 256;
    // CSR build
    k_init <<<(NN + TB - 1) / TB, TB>>>();
    k_count<<<(EE + TB - 1) / TB, TB>>>(ei);
    k_dinv <<<(NN + TB - 1) / TB, TB>>>();
    k_scan <<<1, 1024>>>();
    k_fill <<<(EE + TB - 1) / TB, TB>>>(ei);

    const int gemm_grid = (NN + 63) / 64;
    const int agg_grid  = (NN * 32 + TB - 1) / TB;

    // layer 1
    k_gemm<<<gemm_grid, TB, gemm_smem>>>(x,  W1, h0, 0);
    k_agg <<<agg_grid,  TB>>>(h0, b1, h1);
    // layer 2 (relu fused into gemm input load)
    k_gemm<<<gemm_grid, TB, gemm_smem>>>(h1, W2, h0, 1);
    k_agg <<<agg_grid,  TB>>>(h0, b2, h1);
    // layer 3
    k_gemm<<<gemm_grid, TB, gemm_smem>>>(h1, W3, h0, 1);
    k_agg <<<agg_grid,  TB>>>(h0, b3, h1);

    // pool + head
    k_pool<<<agg_grid, TB>>>(h1, batch);
    k_final<<<1, 128>>>(Wl, bl, out);
}

// round 3
// speedup vs baseline: 1.1684x; 1.1684x over previous
#include <cuda_runtime.h>
#include <math.h>

#define NN   50000
#define EE   800000
#define D    128
#define DOUT 10
#define GG   128
#define NB   250      // scan blocks
#define CH   200      // nodes per scan block (250*200 = 50000)

// ---------------- device scratch ----------------
__device__ float g_h0[(size_t)NN * D];
__device__ float g_h1[(size_t)NN * D];
__device__ int   g_deg[NN];
__device__ float g_dinv[NN];
__device__ int   g_rowptr[NN + 1];
__device__ int   g_fill[NN];
__device__ int   g_colsrc[EE];
__device__ int   g_blocksum[NB];
__device__ int   g_blockbase[NB];
__device__ float g_psum[GG * D];
__device__ int   g_pcnt[GG];

// ---------------- init ----------------
__global__ void k_init() {
    int i = blockIdx.x * blockDim.x + threadIdx.x;
    if (i < NN) { g_deg[i] = 1; g_fill[i] = 0; }
    if (i < GG * D) g_psum[i] = 0.0f;
    if (i < GG) g_pcnt[i] = 0;
}

__global__ void k_count(const int* __restrict__ ei) {
    int e = blockIdx.x * blockDim.x + threadIdx.x;
    if (e < EE) atomicAdd(&g_deg[ei[EE + e]], 1);
}

// per-chunk sum of (deg-1) + dinv, 250 blocks x 256 threads
__global__ void k_partial() {
    __shared__ int red[256];
    const int b = blockIdx.x, t = threadIdx.x;
    int v = 0;
    if (t < CH) {
        int i = b * CH + t;
        int dg = g_deg[i];
        g_dinv[i] = rsqrtf((float)dg);
        v = dg - 1;
    }
    red[t] = v;
    __syncthreads();
    for (int off = 128; off > 0; off >>= 1) {
        if (t < off) red[t] += red[t + off];
        __syncthreads();
    }
    if (t == 0) g_blocksum[b] = red[0];
}

// exclusive scan of 250 block sums, 1 block x 256 threads
__global__ void k_scanblk() {
    __shared__ int s[256];
    const int t = threadIdx.x;
    s[t] = (t < NB) ? g_blocksum[t] : 0;
    __syncthreads();
    for (int off = 1; off < 256; off <<= 1) {
        int v = (t >= off) ? s[t - off] : 0;
        __syncthreads();
        s[t] += v;
        __syncthreads();
    }
    if (t < NB) g_blockbase[t] = (t == 0) ? 0 : s[t - 1];
}

// per-chunk exclusive prefix -> rowptr, 250 blocks x 256 threads
__global__ void k_rowptr() {
    __shared__ int s[256];
    const int b = blockIdx.x, t = threadIdx.x;
    int v = 0;
    if (t < CH) v = g_deg[b * CH + t] - 1;
    s[t] = v;
    __syncthreads();
    for (int off = 1; off < 256; off <<= 1) {
        int u = (t >= off) ? s[t - off] : 0;
        __syncthreads();
        s[t] += u;
        __syncthreads();
    }
    const int base = g_blockbase[b];
    if (t < CH) g_rowptr[b * CH + t] = base + s[t] - v;  // exclusive
    if (b == NB - 1 && t == CH - 1) g_rowptr[NN] = base + s[t];
}

__global__ void k_fill(const int* __restrict__ ei) {
    int e = blockIdx.x * blockDim.x + threadIdx.x;
    if (e < EE) {
        int d = ei[EE + e];
        int s = ei[e];
        int pos = atomicAdd(&g_fill[d], 1);
        g_colsrc[g_rowptr[d] + pos] = s;
    }
}

// ---------------- GEMM: C[NN,128] = relu?(A)[NN,128] @ W[128,128] ----------------
__global__ void k_gemm(const float* __restrict__ A, const float* __restrict__ W,
                       float* __restrict__ C, int relu) {
    extern __shared__ float sm[];
    float* As = sm;               // [64][128]
    float* Ws = sm + 64 * D;      // [128][128]
    const int t = threadIdx.x;
    const int row0 = blockIdx.x * 64;

    for (int j = t; j < (D * D) / 4; j += 256)
        ((float4*)Ws)[j] = ((const float4*)W)[j];

    for (int j = t; j < (64 * D) / 4; j += 256) {
        int r = j >> 5;
        int c4 = j & 31;
        float4 v = make_float4(0.f, 0.f, 0.f, 0.f);
        if (row0 + r < NN)
            v = ((const float4*)(A + (size_t)(row0 + r) * D))[c4];
        if (relu) {
            v.x = fmaxf(v.x, 0.f); v.y = fmaxf(v.y, 0.f);
            v.z = fmaxf(v.z, 0.f); v.w = fmaxf(v.w, 0.f);
        }
        ((float4*)(As + r * D))[c4] = v;
    }
    __syncthreads();

    const int w = t >> 5;   // warp: rows [w*8, w*8+8)
    const int l = t & 31;   // lane: cols [4l, 4l+4)
    float acc[8][4];
    #pragma unroll
    for (int i = 0; i < 8; i++)
        #pragma unroll
        for (int j = 0; j < 4; j++) acc[i][j] = 0.f;

    #pragma unroll 8
    for (int k4 = 0; k4 < D / 4; k4++) {
        float4 a[8];
        #pragma unroll
        for (int i = 0; i < 8; i++)
            a[i] = ((const float4*)(As + (w * 8 + i) * D))[k4];  // broadcast LDS.128
        #pragma unroll
        for (int kk = 0; kk < 4; kk++) {
            float4 b = ((const float4*)(Ws + (k4 * 4 + kk) * D))[l];
            #pragma unroll
            for (int i = 0; i < 8; i++) {
                float av = (kk == 0) ? a[i].x : (kk == 1) ? a[i].y
                         : (kk == 2) ? a[i].z : a[i].w;
                acc[i][0] += av * b.x;
                acc[i][1] += av * b.y;
                acc[i][2] += av * b.z;
                acc[i][3] += av * b.w;
            }
        }
    }

    #pragma unroll
    for (int i = 0; i < 8; i++) {
        int r = row0 + w * 8 + i;
        if (r < NN) {
            float4 o = make_float4(acc[i][0], acc[i][1], acc[i][2], acc[i][3]);
            ((float4*)(C + (size_t)r * D))[l] = o;
        }
    }
}

// ---------------- aggregation: one warp per node ----------------
__global__ void k_agg(const float* __restrict__ H, const float* __restrict__ bias,
                      float* __restrict__ O) {
    int warp = (blockIdx.x * blockDim.x + threadIdx.x) >> 5;
    int lane = threadIdx.x & 31;
    if (warp >= NN) return;
    const int i = warp;
    const float di = g_dinv[i];

    float4 acc = ((const float4*)(H + (size_t)i * D))[lane];
    acc.x *= di; acc.y *= di; acc.z *= di; acc.w *= di;

    const int e0 = g_rowptr[i], e1 = g_rowptr[i + 1];
    for (int e = e0; e < e1; e++) {
        int s = g_colsrc[e];
        float ds = g_dinv[s];
        float4 v = ((const float4*)(H + (size_t)s * D))[lane];
        acc.x += v.x * ds; acc.y += v.y * ds;
        acc.z += v.z * ds; acc.w += v.w * ds;
    }

    float4 b4 = ((const float4*)bias)[lane];
    float4 o;
    o.x = acc.x * di + b4.x;
    o.y = acc.y * di + b4.y;
    o.z = acc.z * di + b4.z;
    o.w = acc.w * di + b4.w;
    ((float4*)(O + (size_t)i * D))[lane] = o;
}

// ---------------- layer-3 aggregation fused with mean-pool accumulate ----------------
__global__ void k_agg_pool(const float* __restrict__ H, const float* __restrict__ bias,
                           const int* __restrict__ batch) {
    int warp = (blockIdx.x * blockDim.x + threadIdx.x) >> 5;
    int lane = threadIdx.x & 31;
    if (warp >= NN) return;
    const int i = warp;
    const float di = g_dinv[i];

    float4 acc = ((const float4*)(H + (size_t)i * D))[lane];
    acc.x *= di; acc.y *= di; acc.z *= di; acc.w *= di;

    const int e0 = g_rowptr[i], e1 = g_rowptr[i + 1];
    for (int e = e0; e < e1; e++) {
        int s = g_colsrc[e];
        float ds = g_dinv[s];
        float4 v = ((const float4*)(H + (size_t)s * D))[lane];
        acc.x += v.x * ds; acc.y += v.y * ds;
        acc.z += v.z * ds; acc.w += v.w * ds;
    }

    float4 b4 = ((const float4*)bias)[lane];
    const int g = batch[i];
    float* dst = g_psum + g * D + lane * 4;
    atomicAdd(dst + 0, acc.x * di + b4.x);
    atomicAdd(dst + 1, acc.y * di + b4.y);
    atomicAdd(dst + 2, acc.z * di + b4.z);
    atomicAdd(dst + 3, acc.w * di + b4.w);
    if (lane == 0) atomicAdd(&g_pcnt[g], 1);
}

// ---------------- head ----------------
__global__ void k_final(const float* __restrict__ Wl, const float* __restrict__ bl,
                        float* __restrict__ out) {
    int g = threadIdx.x;
    if (g >= GG) return;
    float cnt = (float)g_pcnt[g];
    float inv = 1.0f / fmaxf(cnt, 1.0f);
    float logits[DOUT];
    #pragma unroll
    for (int d = 0; d < DOUT; d++) logits[d] = bl[d];
    for (int f = 0; f < D; f++) {
        float p = g_psum[g * D + f] * inv;
        #pragma unroll
        for (int d = 0; d < DOUT; d++)
            logits[d] += p * Wl[f * DOUT + d];
    }
    float m = logits[0];
    #pragma unroll
    for (int d = 1; d < DOUT; d++) m = fmaxf(m, logits[d]);
    float sum = 0.f;
    #pragma unroll
    for (int d = 0; d < DOUT; d++) sum += expf(logits[d] - m);
    float lse = m + logf(sum);
    #pragma unroll
    for (int d = 0; d < DOUT; d++) out[g * DOUT + d] = logits[d] - lse;
}

// ---------------- launch ----------------
extern "C" void kernel_launch(void* const* d_in, const int* in_sizes, int n_in,
                              void* d_out, int out_size) {
    const float* x     = (const float*)d_in[0];
    const int*   ei    = (const int*)d_in[1];
    const int*   batch = (const int*)d_in[2];
    const float* W1 = (const float*)d_in[3];
    const float* b1 = (const float*)d_in[4];
    const float* W2 = (const float*)d_in[5];
    const float* b2 = (const float*)d_in[6];
    const float* W3 = (const float*)d_in[7];
    const float* b3 = (const float*)d_in[8];
    const float* Wl = (const float*)d_in[9];
    const float* bl = (const float*)d_in[10];
    float* out = (float*)d_out;

    const size_t gemm_smem = (64 * D + D * D) * sizeof(float);  // 96 KB
    cudaFuncSetAttribute(k_gemm, cudaFuncAttributeMaxDynamicSharedMemorySize,
                         (int)gemm_smem);

    float *h0, *h1;
    cudaGetSymbolAddress((void**)&h0, g_h0);
    cudaGetSymbolAddress((void**)&h1, g_h1);

    const int TB = 256;
    // CSR build (parallel scan)
    k_init   <<<(NN + TB - 1) / TB, TB>>>();
    k_count  <<<(EE + TB - 1) / TB, TB>>>(ei);
    k_partial<<<NB, 256>>>();
    k_scanblk<<<1, 256>>>();
    k_rowptr <<<NB, 256>>>();
    k_fill   <<<(EE + TB - 1) / TB, TB>>>(ei);

    const int gemm_grid = (NN + 63) / 64;
    const int agg_grid  = (NN * 32 + TB - 1) / TB;

    // layer 1
    k_gemm<<<gemm_grid, TB, gemm_smem>>>(x,  W1, h0, 0);
    k_agg <<<agg_grid,  TB>>>(h0, b1, h1);
    // layer 2
    k_gemm<<<gemm_grid, TB, gemm_smem>>>(h1, W2, h0, 1);
    k_agg <<<agg_grid,  TB>>>(h0, b2, h1);
    // layer 3 (agg fused with pool)
    k_gemm<<<gemm_grid, TB, gemm_smem>>>(h1, W3, h0, 1);
    k_agg_pool<<<agg_grid, TB>>>(h0, b3, batch);

    // head
    k_final<<<1, 128>>>(Wl, bl, out);
}

// round 4
// speedup vs baseline: 1.2870x; 1.1015x over previous
#include <cuda_runtime.h>
#include <math.h>
#include <stdint.h>

#define NN   50000
#define EE   800000
#define D    128
#define DOUT 10
#define GG   128
#define NB   250      // scan blocks
#define CH   200      // nodes per scan block (250*200 = 50000)

// ---------------- device scratch ----------------
__device__ float g_h0[(size_t)NN * D];
__device__ float g_h1[(size_t)NN * D];
__device__ int   g_deg[NN];
__device__ float g_dinv[NN];
__device__ int   g_rowptr[NN + 1];
__device__ int   g_fill[NN];
__device__ int   g_colsrc[EE];
__device__ int   g_blocksum[NB];
__device__ int   g_blockbase[NB];
__device__ float g_psum[GG * D];
__device__ int   g_pcnt[GG];

// ---------------- init ----------------
__global__ void k_init() {
    int i = blockIdx.x * blockDim.x + threadIdx.x;
    if (i < NN) { g_deg[i] = 1; g_fill[i] = 0; }
    if (i < GG * D) g_psum[i] = 0.0f;
    if (i < GG) g_pcnt[i] = 0;
}

__global__ void k_count(const int* __restrict__ ei) {
    int e = blockIdx.x * blockDim.x + threadIdx.x;
    if (e < EE) atomicAdd(&g_deg[ei[EE + e]], 1);
}

// per-chunk sum of (deg-1) + dinv
__global__ void k_partial() {
    __shared__ int red[256];
    const int b = blockIdx.x, t = threadIdx.x;
    int v = 0;
    if (t < CH) {
        int i = b * CH + t;
        int dg = g_deg[i];
        g_dinv[i] = rsqrtf((float)dg);
        v = dg - 1;
    }
    red[t] = v;
    __syncthreads();
    for (int off = 128; off > 0; off >>= 1) {
        if (t < off) red[t] += red[t + off];
        __syncthreads();
    }
    if (t == 0) g_blocksum[b] = red[0];
}

__global__ void k_scanblk() {
    __shared__ int s[256];
    const int t = threadIdx.x;
    s[t] = (t < NB) ? g_blocksum[t] : 0;
    __syncthreads();
    for (int off = 1; off < 256; off <<= 1) {
        int v = (t >= off) ? s[t - off] : 0;
        __syncthreads();
        s[t] += v;
        __syncthreads();
    }
    if (t < NB) g_blockbase[t] = (t == 0) ? 0 : s[t - 1];
}

__global__ void k_rowptr() {
    __shared__ int s[256];
    const int b = blockIdx.x, t = threadIdx.x;
    int v = 0;
    if (t < CH) v = g_deg[b * CH + t] - 1;
    s[t] = v;
    __syncthreads();
    for (int off = 1; off < 256; off <<= 1) {
        int u = (t >= off) ? s[t - off] : 0;
        __syncthreads();
        s[t] += u;
        __syncthreads();
    }
    const int base = g_blockbase[b];
    if (t < CH) g_rowptr[b * CH + t] = base + s[t] - v;
    if (b == NB - 1 && t == CH - 1) g_rowptr[NN] = base + s[t];
}

__global__ void k_fill(const int* __restrict__ ei) {
    int e = blockIdx.x * blockDim.x + threadIdx.x;
    if (e < EE) {
        int d = ei[EE + e];
        int s = ei[e];
        int pos = atomicAdd(&g_fill[d], 1);
        g_colsrc[g_rowptr[d] + pos] = s;
    }
}

// ---------------- tf32 tensor-core GEMM ----------------
// C[NN,128] = relu?(A)[NN,128] @ W[128,128]
// Block: 256 thr (8 warps), tile M=128 x N=128 x K=128.
// Warps: 4 in M (32 rows each) x 2 in N (64 cols each).
// Smem: As[128][132] tf32, Wt[128][132] tf32 (W transposed: Wt[n][k]).
// Stride 132 -> bank = (4*quad + rem) mod 32: conflict-free fragment loads.

#define SMS 132
#define GEMM_SMEM (2 * 128 * SMS * sizeof(float))

__device__ __forceinline__ uint32_t f2tf32(float f) {
    uint32_t u;
    asm("cvt.rna.tf32.f32 %0, %1;" : "=r"(u) : "f"(f));
    return u;
}

#define MMA_TF32(cc, aa, b0, b1)                                          \
    asm volatile("mma.sync.aligned.m16n8k8.row.col.f32.tf32.tf32.f32 "    \
                 "{%0,%1,%2,%3}, {%4,%5,%6,%7}, {%8,%9}, {%0,%1,%2,%3};"  \
                 : "+f"(cc[0]), "+f"(cc[1]), "+f"(cc[2]), "+f"(cc[3])     \
                 : "r"(aa[0]), "r"(aa[1]), "r"(aa[2]), "r"(aa[3]),        \
                   "r"(b0), "r"(b1))

__global__ void k_gemm_tc(const float* __restrict__ A, const float* __restrict__ W,
                          float* __restrict__ C, int relu) {
    extern __shared__ float sm[];
    float* As = sm;                 // [128][132]
    float* Wt = sm + 128 * SMS;     // [128][132]  Wt[n][k]
    const int t = threadIdx.x;
    const int row0 = blockIdx.x * 128;

    // stage Wt (transpose + tf32 round): coalesced read of W[k][n]
    for (int idx = t; idx < D * D; idx += 256) {
        int k = idx >> 7, n = idx & 127;
        Wt[n * SMS + k] = __uint_as_float(f2tf32(W[idx]));
    }

    // stage As (relu + tf32 round): float4 coalesced read, float4 smem write
    for (int j = t; j < (128 * D) / 4; j += 256) {
        int r = j >> 5;          // 32 float4 per row
        int c4 = (j & 31) * 4;
        float4 v = make_float4(0.f, 0.f, 0.f, 0.f);
        if (row0 + r < NN)
            v = *(const float4*)(A + (size_t)(row0 + r) * D + c4);
        if (relu) {
            v.x = fmaxf(v.x, 0.f); v.y = fmaxf(v.y, 0.f);
            v.z = fmaxf(v.z, 0.f); v.w = fmaxf(v.w, 0.f);
        }
        float4 o;
        o.x = __uint_as_float(f2tf32(v.x));
        o.y = __uint_as_float(f2tf32(v.y));
        o.z = __uint_as_float(f2tf32(v.z));
        o.w = __uint_as_float(f2tf32(v.w));
        *(float4*)(As + r * SMS + c4) = o;
    }
    __syncthreads();

    const int w    = t >> 5;
    const int lane = t & 31;
    const int wm   = w & 3;     // 4 warps in M: rows [wm*32, wm*32+32)
    const int wn   = w >> 2;    // 2 warps in N: cols [wn*64, wn*64+64)
    const int quad = lane >> 2; // 0..7
    const int rem  = lane & 3;  // 0..3

    float acc[2][8][4];
    #pragma unroll
    for (int m = 0; m < 2; m++)
        #pragma unroll
        for (int j = 0; j < 8; j++)
            #pragma unroll
            for (int r = 0; r < 4; r++) acc[m][j][r] = 0.f;

    const float* Ab = As + (wm * 32 + quad) * SMS + rem;
    const float* Bb = Wt + (wn * 64 + quad) * SMS + rem;

    #pragma unroll
    for (int ks = 0; ks < 16; ks++) {
        const int k0 = ks * 8;
        uint32_t a[2][4];
        #pragma unroll
        for (int m = 0; m < 2; m++) {
            const float* p = Ab + m * 16 * SMS + k0;
            a[m][0] = __float_as_uint(p[0]);
            a[m][1] = __float_as_uint(p[8 * SMS]);
            a[m][2] = __float_as_uint(p[4]);
            a[m][3] = __float_as_uint(p[8 * SMS + 4]);
        }
        #pragma unroll
        for (int j = 0; j < 8; j++) {
            const float* q = Bb + j * 8 * SMS + k0;
            uint32_t b0 = __float_as_uint(q[0]);
            uint32_t b1 = __float_as_uint(q[4]);
            MMA_TF32(acc[0][j], a[0], b0, b1);
            MMA_TF32(acc[1][j], a[1], b0, b1);
        }
    }

    // epilogue: c0/c1 -> (r, 2c),(r,2c+1); c2/c3 -> (r+8, ...)
    #pragma unroll
    for (int m = 0; m < 2; m++) {
        int r = row0 + wm * 32 + m * 16 + quad;
        #pragma unroll
        for (int j = 0; j < 8; j++) {
            int cb = wn * 64 + j * 8 + rem * 2;
            if (r < NN)
                *(float2*)(C + (size_t)r * D + cb) =
                    make_float2(acc[m][j][0], acc[m][j][1]);
            if (r + 8 < NN)
                *(float2*)(C + (size_t)(r + 8) * D + cb) =
                    make_float2(acc[m][j][2], acc[m][j][3]);
        }
    }
}

// ---------------- aggregation: one warp per node ----------------
__global__ void k_agg(const float* __restrict__ H, const float* __restrict__ bias,
                      float* __restrict__ O) {
    int warp = (blockIdx.x * blockDim.x + threadIdx.x) >> 5;
    int lane = threadIdx.x & 31;
    if (warp >= NN) return;
    const int i = warp;
    const float di = g_dinv[i];

    float4 acc = ((const float4*)(H + (size_t)i * D))[lane];
    acc.x *= di; acc.y *= di; acc.z *= di; acc.w *= di;

    const int e0 = g_rowptr[i], e1 = g_rowptr[i + 1];
    for (int e = e0; e < e1; e++) {
        int s = g_colsrc[e];
        float ds = g_dinv[s];
        float4 v = ((const float4*)(H + (size_t)s * D))[lane];
        acc.x += v.x * ds; acc.y += v.y * ds;
        acc.z += v.z * ds; acc.w += v.w * ds;
    }

    float4 b4 = ((const float4*)bias)[lane];
    float4 o;
    o.x = acc.x * di + b4.x;
    o.y = acc.y * di + b4.y;
    o.z = acc.z * di + b4.z;
    o.w = acc.w * di + b4.w;
    ((float4*)(O + (size_t)i * D))[lane] = o;
}

// ---------------- layer-3 aggregation fused with mean-pool accumulate ----------------
__global__ void k_agg_pool(const float* __restrict__ H, const float* __restrict__ bias,
                           const int* __restrict__ batch) {
    int warp = (blockIdx.x * blockDim.x + threadIdx.x) >> 5;
    int lane = threadIdx.x & 31;
    if (warp >= NN) return;
    const int i = warp;
    const float di = g_dinv[i];

    float4 acc = ((const float4*)(H + (size_t)i * D))[lane];
    acc.x *= di; acc.y *= di; acc.z *= di; acc.w *= di;

    const int e0 = g_rowptr[i], e1 = g_rowptr[i + 1];
    for (int e = e0; e < e1; e++) {
        int s = g_colsrc[e];
        float ds = g_dinv[s];
        float4 v = ((const float4*)(H + (size_t)s * D))[lane];
        acc.x += v.x * ds; acc.y += v.y * ds;
        acc.z += v.z * ds; acc.w += v.w * ds;
    }

    float4 b4 = ((const float4*)bias)[lane];
    const int g = batch[i];
    float* dst = g_psum + g * D + lane * 4;
    atomicAdd(dst + 0, acc.x * di + b4.x);
    atomicAdd(dst + 1, acc.y * di + b4.y);
    atomicAdd(dst + 2, acc.z * di + b4.z);
    atomicAdd(dst + 3, acc.w * di + b4.w);
    if (lane == 0) atomicAdd(&g_pcnt[g], 1);
}

// ---------------- head ----------------
__global__ void k_final(const float* __restrict__ Wl, const float* __restrict__ bl,
                        float* __restrict__ out) {
    int g = threadIdx.x;
    if (g >= GG) return;
    float cnt = (float)g_pcnt[g];
    float inv = 1.0f / fmaxf(cnt, 1.0f);
    float logits[DOUT];
    #pragma unroll
    for (int d = 0; d < DOUT; d++) logits[d] = bl[d];
    for (int f = 0; f < D; f++) {
        float p = g_psum[g * D + f] * inv;
        #pragma unroll
        for (int d = 0; d < DOUT; d++)
            logits[d] += p * Wl[f * DOUT + d];
    }
    float m = logits[0];
    #pragma unroll
    for (int d = 1; d < DOUT; d++) m = fmaxf(m, logits[d]);
    float sum = 0.f;
    #pragma unroll
    for (int d = 0; d < DOUT; d++) sum += expf(logits[d] - m);
    float lse = m + logf(sum);
    #pragma unroll
    for (int d = 0; d < DOUT; d++) out[g * DOUT + d] = logits[d] - lse;
}

// ---------------- launch ----------------
extern "C" void kernel_launch(void* const* d_in, const int* in_sizes, int n_in,
                              void* d_out, int out_size) {
    const float* x     = (const float*)d_in[0];
    const int*   ei    = (const int*)d_in[1];
    const int*   batch = (const int*)d_in[2];
    const float* W1 = (const float*)d_in[3];
    const float* b1 = (const float*)d_in[4];
    const float* W2 = (const float*)d_in[5];
    const float* b2 = (const float*)d_in[6];
    const float* W3 = (const float*)d_in[7];
    const float* b3 = (const float*)d_in[8];
    const float* Wl = (const float*)d_in[9];
    const float* bl = (const float*)d_in[10];
    float* out = (float*)d_out;

    cudaFuncSetAttribute(k_gemm_tc, cudaFuncAttributeMaxDynamicSharedMemorySize,
                         (int)GEMM_SMEM);

    float *h0, *h1;
    cudaGetSymbolAddress((void**)&h0, g_h0);
    cudaGetSymbolAddress((void**)&h1, g_h1);

    const int TB = 256;
    // CSR build
    k_init   <<<(NN + TB - 1) / TB, TB>>>();
    k_count  <<<(EE + TB - 1) / TB, TB>>>(ei);
    k_partial<<<NB, 256>>>();
    k_scanblk<<<1, 256>>>();
    k_rowptr <<<NB, 256>>>();
    k_fill   <<<(EE + TB - 1) / TB, TB>>>(ei);

    const int gemm_grid = (NN + 127) / 128;   // 391
    const int agg_grid  = (NN * 32 + TB - 1) / TB;

    // layer 1
    k_gemm_tc<<<gemm_grid, TB, GEMM_SMEM>>>(x,  W1, h0, 0);
    k_agg    <<<agg_grid,  TB>>>(h0, b1, h1);
    // layer 2
    k_gemm_tc<<<gemm_grid, TB, GEMM_SMEM>>>(h1, W2, h0, 1);
    k_agg    <<<agg_grid,  TB>>>(h0, b2, h1);
    // layer 3 (agg fused with pool)
    k_gemm_tc<<<gemm_grid, TB, GEMM_SMEM>>>(h1, W3, h0, 1);
    k_agg_pool<<<agg_grid, TB>>>(h0, b3, batch);

    // head
    k_final<<<1, 128>>>(Wl, bl, out);
}

// round 5
// speedup vs baseline: 1.7093x; 1.3281x over previous
#include <cuda_runtime.h>
#include <cuda_fp16.h>
#include <math.h>
#include <stdint.h>

#define NN   50000
#define EE   800000
#define D    128
#define DOUT 10
#define GG   128
#define NB   250
#define CH   200

// ---------------- device scratch ----------------
__device__ __half g_h0[(size_t)NN * D];   // gemm out (fp16)
__device__ __half g_h1[(size_t)NN * D];   // agg out (fp16)
__device__ int    g_deg[NN];
__device__ float  g_dinv[NN];
__device__ int    g_rowptr[NN + 1];
__device__ int    g_fill[NN];
__device__ int    g_colsrc[EE];
__device__ int    g_blocksum[NB];
__device__ int    g_blockbase[NB];
__device__ float  g_psum[GG * D];
__device__ int    g_pcnt[GG];

// ---------------- CSR build ----------------
__global__ void k_init() {
    int i = blockIdx.x * blockDim.x + threadIdx.x;
    if (i < NN) { g_deg[i] = 1; g_fill[i] = 0; }
    if (i < GG * D) g_psum[i] = 0.0f;
    if (i < GG) g_pcnt[i] = 0;
}

__global__ void k_count(const int* __restrict__ ei) {
    int e = blockIdx.x * blockDim.x + threadIdx.x;
    if (e < EE) atomicAdd(&g_deg[ei[EE + e]], 1);
}

__global__ void k_partial() {
    __shared__ int red[256];
    const int b = blockIdx.x, t = threadIdx.x;
    int v = 0;
    if (t < CH) {
        int i = b * CH + t;
        int dg = g_deg[i];
        g_dinv[i] = rsqrtf((float)dg);
        v = dg - 1;
    }
    red[t] = v;
    __syncthreads();
    for (int off = 128; off > 0; off >>= 1) {
        if (t < off) red[t] += red[t + off];
        __syncthreads();
    }
    if (t == 0) g_blocksum[b] = red[0];
}

__global__ void k_scanblk() {
    __shared__ int s[256];
    const int t = threadIdx.x;
    s[t] = (t < NB) ? g_blocksum[t] : 0;
    __syncthreads();
    for (int off = 1; off < 256; off <<= 1) {
        int v = (t >= off) ? s[t - off] : 0;
        __syncthreads();
        s[t] += v;
        __syncthreads();
    }
    if (t < NB) g_blockbase[t] = (t == 0) ? 0 : s[t - 1];
}

__global__ void k_rowptr() {
    __shared__ int s[256];
    const int b = blockIdx.x, t = threadIdx.x;
    int v = 0;
    if (t < CH) v = g_deg[b * CH + t] - 1;
    s[t] = v;
    __syncthreads();
    for (int off = 1; off < 256; off <<= 1) {
        int u = (t >= off) ? s[t - off] : 0;
        __syncthreads();
        s[t] += u;
        __syncthreads();
    }
    const int base = g_blockbase[b];
    if (t < CH) g_rowptr[b * CH + t] = base + s[t] - v;
    if (b == NB - 1 && t == CH - 1) g_rowptr[NN] = base + s[t];
}

__global__ void k_fill(const int* __restrict__ ei) {
    int e = blockIdx.x * blockDim.x + threadIdx.x;
    if (e < EE) {
        int d = ei[EE + e];
        int s = ei[e];
        int pos = atomicAdd(&g_fill[d], 1);
        g_colsrc[g_rowptr[d] + pos] = s;
    }
}

// ---------------- fp16 tensor-core GEMM ----------------
// C[NN,128](fp16) = relu?(A)[NN,128] @ W[128,128](fp32->fp16)
// Block 256 thr (8 warps), tile 128x128x128, warps 4(M)x2(N), 2 CTAs/SM.
// Smem: As[128][136] half + Wt[128][136] half (Wt[n][k]) = 68 KB.

#define SMSH 136
#define GEMM_SMEM (2 * 128 * SMSH * sizeof(__half))

#define MMA_F16(cc, a0, a1, a2, a3, b0, b1)                               \
    asm volatile("mma.sync.aligned.m16n8k16.row.col.f32.f16.f16.f32 "     \
                 "{%0,%1,%2,%3}, {%4,%5,%6,%7}, {%8,%9}, {%0,%1,%2,%3};"  \
                 : "+f"(cc[0]), "+f"(cc[1]), "+f"(cc[2]), "+f"(cc[3])     \
                 : "r"(a0), "r"(a1), "r"(a2), "r"(a3), "r"(b0), "r"(b1))

template <bool IN_HALF, bool RELU>
__global__ void __launch_bounds__(256, 2)
k_gemm_h(const void* __restrict__ Ain, const float* __restrict__ W,
         __half* __restrict__ C) {
    extern __shared__ __half smh[];
    __half* As = smh;                 // [128][136]
    __half* Wt = smh + 128 * SMSH;    // [128][136]  Wt[n][k]
    const int t = threadIdx.x;
    const int row0 = blockIdx.x * 128;

    // stage Wt: coalesced read of W[k][n] fp32, scattered half store
    for (int idx = t; idx < D * D; idx += 256) {
        int k = idx >> 7, n = idx & 127;
        Wt[n * SMSH + k] = __float2half_rn(W[idx]);
    }

    // stage As
    if (IN_HALF) {
        const __half* A = (const __half*)Ain;
        const __half2 z2 = __float2half2_rn(0.f);
        for (int j = t; j < (128 * D) / 8; j += 256) {
            int r = j >> 4;              // 16 uint4 per row
            int c8 = (j & 15) * 8;
            uint4 u = make_uint4(0, 0, 0, 0);
            if (row0 + r < NN)
                u = *(const uint4*)(A + (size_t)(row0 + r) * D + c8);
            if (RELU) {
                __half2* h = (__half2*)&u;
                #pragma unroll
                for (int q = 0; q < 4; q++) h[q] = __hmax2(h[q], z2);
            }
            *(uint4*)(As + r * SMSH + c8) = u;
        }
    } else {
        const float* A = (const float*)Ain;
        for (int j = t; j < (128 * D) / 4; j += 256) {
            int r = j >> 5;
            int c4 = (j & 31) * 4;
            float4 v = make_float4(0.f, 0.f, 0.f, 0.f);
            if (row0 + r < NN)
                v = *(const float4*)(A + (size_t)(row0 + r) * D + c4);
            __half2 h01 = __floats2half2_rn(v.x, v.y);
            __half2 h23 = __floats2half2_rn(v.z, v.w);
            uint2 u;
            u.x = *(uint32_t*)&h01;
            u.y = *(uint32_t*)&h23;
            *(uint2*)(As + r * SMSH + c4) = u;
        }
    }
    __syncthreads();

    const int w    = t >> 5;
    const int lane = t & 31;
    const int wm   = w & 3;     // rows [wm*32, +32)
    const int wn   = w >> 2;    // cols [wn*64, +64)
    const int quad = lane >> 2;
    const int rem  = lane & 3;

    float acc[2][8][4];
    #pragma unroll
    for (int m = 0; m < 2; m++)
        #pragma unroll
        for (int j = 0; j < 8; j++)
            #pragma unroll
            for (int r = 0; r < 4; r++) acc[m][j][r] = 0.f;

    const __half* Ab = As + (wm * 32 + quad) * SMSH + 2 * rem;
    const __half* Bb = Wt + (wn * 64 + quad) * SMSH + 2 * rem;

    #pragma unroll
    for (int ks = 0; ks < 8; ks++) {
        const int k0 = ks * 16;
        uint32_t a[2][4];
        #pragma unroll
        for (int m = 0; m < 2; m++) {
            const __half* p = Ab + m * 16 * SMSH + k0;
            a[m][0] = *(const uint32_t*)(p);
            a[m][1] = *(const uint32_t*)(p + 8 * SMSH);
            a[m][2] = *(const uint32_t*)(p + 8);
            a[m][3] = *(const uint32_t*)(p + 8 * SMSH + 8);
        }
        #pragma unroll
        for (int j = 0; j < 8; j++) {
            const __half* q = Bb + j * 8 * SMSH + k0;
            uint32_t b0 = *(const uint32_t*)(q);
            uint32_t b1 = *(const uint32_t*)(q + 8);
            MMA_F16(acc[0][j], a[0][0], a[0][1], a[0][2], a[0][3], b0, b1);
            MMA_F16(acc[1][j], a[1][0], a[1][1], a[1][2], a[1][3], b0, b1);
        }
    }

    // epilogue: fp32 acc -> fp16, half2 stores
    #pragma unroll
    for (int m = 0; m < 2; m++) {
        int r = row0 + wm * 32 + m * 16 + quad;
        #pragma unroll
        for (int j = 0; j < 8; j++) {
            int cb = wn * 64 + j * 8 + rem * 2;
            if (r < NN) {
                __half2 h = __floats2half2_rn(acc[m][j][0], acc[m][j][1]);
                *(uint32_t*)(C + (size_t)r * D + cb) = *(uint32_t*)&h;
            }
            if (r + 8 < NN) {
                __half2 h = __floats2half2_rn(acc[m][j][2], acc[m][j][3]);
                *(uint32_t*)(C + (size_t)(r + 8) * D + cb) = *(uint32_t*)&h;
            }
        }
    }
}

// ---------------- aggregation (fp16 gather, fp32 accum) ----------------
__device__ __forceinline__ void agg_accum(const __half* H, int s, float ds,
                                          int lane, float* acc) {
    uint2 u = ((const uint2*)(H + (size_t)s * D))[lane];
    __half2 p0 = *(__half2*)&u.x;
    __half2 p1 = *(__half2*)&u.y;
    float2 f0 = __half22float2(p0);
    float2 f1 = __half22float2(p1);
    acc[0] += f0.x * ds; acc[1] += f0.y * ds;
    acc[2] += f1.x * ds; acc[3] += f1.y * ds;
}

__global__ void k_agg(const __half* __restrict__ H, const float* __restrict__ bias,
                      __half* __restrict__ O) {
    int warp = (blockIdx.x * blockDim.x + threadIdx.x) >> 5;
    int lane = threadIdx.x & 31;
    if (warp >= NN) return;
    const int i = warp;
    const float di = g_dinv[i];

    float acc[4] = {0.f, 0.f, 0.f, 0.f};
    agg_accum(H, i, di, lane, acc);          // self loop (scaled by di)

    const int e0 = g_rowptr[i], e1 = g_rowptr[i + 1];
    for (int e = e0; e < e1; e++) {
        int s = g_colsrc[e];
        agg_accum(H, s, g_dinv[s], lane, acc);
    }

    float4 b4 = ((const float4*)bias)[lane];
    __half2 o01 = __floats2half2_rn(acc[0] * di + b4.x, acc[1] * di + b4.y);
    __half2 o23 = __floats2half2_rn(acc[2] * di + b4.z, acc[3] * di + b4.w);
    uint2 u;
    u.x = *(uint32_t*)&o01;
    u.y = *(uint32_t*)&o23;
    ((uint2*)(O + (size_t)i * D))[lane] = u;
}

// layer-3 aggregation fused with mean-pool accumulate (fp32 atomics)
__global__ void k_agg_pool(const __half* __restrict__ H, const float* __restrict__ bias,
                           const int* __restrict__ batch) {
    int warp = (blockIdx.x * blockDim.x + threadIdx.x) >> 5;
    int lane = threadIdx.x & 31;
    if (warp >= NN) return;
    const int i = warp;
    const float di = g_dinv[i];

    float acc[4] = {0.f, 0.f, 0.f, 0.f};
    agg_accum(H, i, di, lane, acc);

    const int e0 = g_rowptr[i], e1 = g_rowptr[i + 1];
    for (int e = e0; e < e1; e++) {
        int s = g_colsrc[e];
        agg_accum(H, s, g_dinv[s], lane, acc);
    }

    float4 b4 = ((const float4*)bias)[lane];
    const int g = batch[i];
    float* dst = g_psum + g * D + lane * 4;
    atomicAdd(dst + 0, acc[0] * di + b4.x);
    atomicAdd(dst + 1, acc[1] * di + b4.y);
    atomicAdd(dst + 2, acc[2] * di + b4.z);
    atomicAdd(dst + 3, acc[3] * di + b4.w);
    if (lane == 0) atomicAdd(&g_pcnt[g], 1);
}

// ---------------- head ----------------
__global__ void k_final(const float* __restrict__ Wl, const float* __restrict__ bl,
                        float* __restrict__ out) {
    int g = threadIdx.x;
    if (g >= GG) return;
    float cnt = (float)g_pcnt[g];
    float inv = 1.0f / fmaxf(cnt, 1.0f);
    float logits[DOUT];
    #pragma unroll
    for (int d = 0; d < DOUT; d++) logits[d] = bl[d];
    for (int f = 0; f < D; f++) {
        float p = g_psum[g * D + f] * inv;
        #pragma unroll
        for (int d = 0; d < DOUT; d++)
            logits[d] += p * Wl[f * DOUT + d];
    }
    float m = logits[0];
    #pragma unroll
    for (int d = 1; d < DOUT; d++) m = fmaxf(m, logits[d]);
    float sum = 0.f;
    #pragma unroll
    for (int d = 0; d < DOUT; d++) sum += expf(logits[d] - m);
    float lse = m + logf(sum);
    #pragma unroll
    for (int d = 0; d < DOUT; d++) out[g * DOUT + d] = logits[d] - lse;
}

// ---------------- launch ----------------
extern "C" void kernel_launch(void* const* d_in, const int* in_sizes, int n_in,
                              void* d_out, int out_size) {
    const float* x     = (const float*)d_in[0];
    const int*   ei    = (const int*)d_in[1];
    const int*   batch = (const int*)d_in[2];
    const float* W1 = (const float*)d_in[3];
    const float* b1 = (const float*)d_in[4];
    const float* W2 = (const float*)d_in[5];
    const float* b2 = (const float*)d_in[6];
    const float* W3 = (const float*)d_in[7];
    const float* b3 = (const float*)d_in[8];
    const float* Wl = (const float*)d_in[9];
    const float* bl = (const float*)d_in[10];
    float* out = (float*)d_out;

    cudaFuncSetAttribute(k_gemm_h<false, false>,
                         cudaFuncAttributeMaxDynamicSharedMemorySize, (int)GEMM_SMEM);
    cudaFuncSetAttribute(k_gemm_h<true, true>,
                         cudaFuncAttributeMaxDynamicSharedMemorySize, (int)GEMM_SMEM);

    __half *h0, *h1;
    cudaGetSymbolAddress((void**)&h0, g_h0);
    cudaGetSymbolAddress((void**)&h1, g_h1);

    const int TB = 256;
    // CSR build
    k_init   <<<(NN + TB - 1) / TB, TB>>>();
    k_count  <<<(EE + TB - 1) / TB, TB>>>(ei);
    k_partial<<<NB, 256>>>();
    k_scanblk<<<1, 256>>>();
    k_rowptr <<<NB, 256>>>();
    k_fill   <<<(EE + TB - 1) / TB, TB>>>(ei);

    const int gemm_grid = (NN + 127) / 128;   // 391
    const int agg_grid  = (NN * 32 + TB - 1) / TB;

    // layer 1
    k_gemm_h<false, false><<<gemm_grid, TB, GEMM_SMEM>>>(x,  W1, h0);
    k_agg<<<agg_grid, TB>>>(h0, b1, h1);
    // layer 2
    k_gemm_h<true, true><<<gemm_grid, TB, GEMM_SMEM>>>(h1, W2, h0);
    k_agg<<<agg_grid, TB>>>(h0, b2, h1);
    // layer 3 (agg fused with pool)
    k_gemm_h<true, true><<<gemm_grid, TB, GEMM_SMEM>>>(h1, W3, h0);
    k_agg_pool<<<agg_grid, TB>>>(h0, b3, batch);

    // head
    k_final<<<1, 128>>>(Wl, bl, out);
}